// round 1
// baseline (speedup 1.0000x reference)
#include <cuda_runtime.h>
#include <cuda_bf16.h>
#include <cstdint>

#define N_NODES 20000
#define E_EDGES 640000
#define P_DIM   12
#define H_DIM   128
#define O_DIM   12

// ---------------- scratch (no dynamic allocation allowed) ----------------
__device__ float g_deg [N_NODES];
__device__ float g_dinv[N_NODES];
__device__ float g_agg [N_NODES * P_DIM];
__device__ float g_az[H_DIM], g_bz[H_DIM], g_ah[H_DIM], g_bh[H_DIM];
__device__ float g_probs[P_DIM];

// ---------------- init: deg=1 (self loop), agg=0 ----------------
__global__ void k_init() {
    int i = blockIdx.x * blockDim.x + threadIdx.x;
    if (i < N_NODES * P_DIM) g_agg[i] = 0.0f;
    if (i < N_NODES)         g_deg[i] = 1.0f;   // self-loop weight
}

// ---------------- degree accumulation ----------------
__global__ void k_deg(const int* __restrict__ ei, const float* __restrict__ ew) {
    int e = blockIdx.x * blockDim.x + threadIdx.x;
    if (e >= E_EDGES) return;
    int d = ei[E_EDGES + e];
    atomicAdd(&g_deg[d], ew[e]);
}

// ---------------- dinv ----------------
__global__ void k_dinv() {
    int n = blockIdx.x * blockDim.x + threadIdx.x;
    if (n >= N_NODES) return;
    float d = g_deg[n];
    g_dinv[n] = (d > 0.0f) ? rsqrtf(d) : 0.0f;
}

// ---------------- fold H x H matmuls into 128-vectors + softmax ----------------
__global__ void k_prep(const float* __restrict__ cwz, const float* __restrict__ cbz,
                       const float* __restrict__ Wz,  const float* __restrict__ lbz,
                       const float* __restrict__ cwh, const float* __restrict__ cbh,
                       const float* __restrict__ Wh,  const float* __restrict__ lbh,
                       const float* __restrict__ att) {
    int k = threadIdx.x;   // 128 threads
    float az = 0.f, bz = 0.f, ah = 0.f, bh = 0.f;
    for (int h = 0; h < H_DIM; h++) {
        float wz = Wz[h * H_DIM + k];
        float wh = Wh[h * H_DIM + k];
        az = fmaf(cwz[h], wz, az);
        bz = fmaf(cbz[h], wz, bz);
        ah = fmaf(cwh[h], wh, ah);
        bh = fmaf(cbh[h], wh, bh);
    }
    g_az[k] = az;  g_bz[k] = bz + lbz[k];
    g_ah[k] = ah;  g_bh[k] = bh + lbh[k];
    if (k == 0) {
        float m = -1e30f;
        for (int p = 0; p < P_DIM; p++) m = fmaxf(m, att[p]);
        float ex[P_DIM]; float s = 0.f;
        for (int p = 0; p < P_DIM; p++) { ex[p] = __expf(att[p] - m); s += ex[p]; }
        float inv = 1.0f / s;
        for (int p = 0; p < P_DIM; p++) g_probs[p] = ex[p] * inv;
    }
}

// ---------------- edge scatter: agg[dst] += norm * x[src] ----------------
__device__ __forceinline__ void red_add_v4(float* addr, float4 v) {
    asm volatile("red.global.add.v4.f32 [%0], {%1, %2, %3, %4};"
                 :: "l"(addr), "f"(v.x), "f"(v.y), "f"(v.z), "f"(v.w)
                 : "memory");
}

__global__ void k_edge(const int* __restrict__ ei, const float* __restrict__ ew,
                       const float* __restrict__ x) {
    int e = blockIdx.x * blockDim.x + threadIdx.x;
    if (e >= E_EDGES) return;
    int s = ei[e];
    int d = ei[E_EDGES + e];
    float norm = g_dinv[s] * ew[e] * g_dinv[d];
    const float4* xr = (const float4*)(x + (size_t)s * P_DIM);   // 48B row, 16B aligned
    float*        ar = g_agg + (size_t)d * P_DIM;
#pragma unroll
    for (int j = 0; j < 3; j++) {
        float4 v = xr[j];
        v.x *= norm; v.y *= norm; v.z *= norm; v.w *= norm;
        red_add_v4(ar + 4 * j, v);
    }
}

// ---------------- node kernel: one warp per node ----------------
__global__ void __launch_bounds__(256) k_node(const float* __restrict__ x,
                                              const float* __restrict__ wout,
                                              const float* __restrict__ bout,
                                              float* __restrict__ out) {
    __shared__ float s_az[H_DIM], s_bz[H_DIM], s_ah[H_DIM], s_bh[H_DIM];
    __shared__ float s_woutT[O_DIM * H_DIM];
    __shared__ float s_probs[P_DIM], s_bout[O_DIM];

    int tid = threadIdx.x;
    for (int i = tid; i < H_DIM; i += 256) {
        s_az[i] = g_az[i]; s_bz[i] = g_bz[i];
        s_ah[i] = g_ah[i]; s_bh[i] = g_bh[i];
    }
    for (int i = tid; i < H_DIM * O_DIM; i += 256) {
        int k = i / O_DIM, o = i % O_DIM;
        s_woutT[o * H_DIM + k] = wout[i];       // transpose -> conflict-free LDS
    }
    if (tid < P_DIM) s_probs[tid] = g_probs[tid];
    if (tid < O_DIM) s_bout[tid]  = bout[tid];
    __syncthreads();

    int warp = tid >> 5, lane = tid & 31;
    int n = blockIdx.x * 8 + warp;
    if (n >= N_NODES) return;

    float dv  = g_dinv[n];
    float dv2 = dv * dv;                         // self-loop norm
    const float4* ar = (const float4*)(g_agg + (size_t)n * P_DIM);
    const float4* xr = (const float4*)(x     + (size_t)n * P_DIM);
    float a[P_DIM];
#pragma unroll
    for (int j = 0; j < 3; j++) {
        float4 av = ar[j];
        float4 xv = xr[j];
        a[4*j + 0] = fmaf(dv2, xv.x, av.x);
        a[4*j + 1] = fmaf(dv2, xv.y, av.y);
        a[4*j + 2] = fmaf(dv2, xv.z, av.z);
        a[4*j + 3] = fmaf(dv2, xv.w, av.w);
    }

    float acc[4] = {0.f, 0.f, 0.f, 0.f};
#pragma unroll
    for (int p = 0; p < P_DIM; p++) {
        float ap = a[p];
        float wp = s_probs[p];
#pragma unroll
        for (int j = 0; j < 4; j++) {
            int k = lane + 32 * j;
            // (1 - sigmoid(zs)) = 1 / (1 + exp(zs))
            float zs  = fmaf(ap, s_az[k], s_bz[k]);
            float omz = __fdividef(1.0f, 1.0f + __expf(zs));
            // tanh(hs), overflow-safe via |hs|
            float hs  = fmaf(ap, s_ah[k], s_bh[k]);
            float t   = __expf(-2.0f * fabsf(hs));
            float ht  = __fdividef(1.0f - t, 1.0f + t);
            ht = copysignf(ht, hs);
            acc[j] = fmaf(wp * omz, ht, acc[j]);
        }
    }

    // elu + out matvec (O=12)
    float o_acc[O_DIM];
#pragma unroll
    for (int o = 0; o < O_DIM; o++) o_acc[o] = 0.f;
#pragma unroll
    for (int j = 0; j < 4; j++) {
        float hk = acc[j];
        hk = (hk > 0.f) ? hk : (__expf(hk) - 1.0f);
        int k = lane + 32 * j;
#pragma unroll
        for (int o = 0; o < O_DIM; o++)
            o_acc[o] = fmaf(hk, s_woutT[o * H_DIM + k], o_acc[o]);
    }
#pragma unroll
    for (int off = 16; off > 0; off >>= 1) {
#pragma unroll
        for (int o = 0; o < O_DIM; o++)
            o_acc[o] += __shfl_xor_sync(0xffffffffu, o_acc[o], off);
    }
    if (lane == 0) {
        float* op = out + (size_t)n * O_DIM;
#pragma unroll
        for (int o = 0; o < O_DIM; o++) op[o] = o_acc[o] + s_bout[o];
    }
}

// ---------------- launch ----------------
extern "C" void kernel_launch(void* const* d_in, const int* in_sizes, int n_in,
                              void* d_out, int out_size) {
    const float* x    = (const float*)d_in[0];
    const int*   ei   = (const int*)  d_in[1];
    const float* ew   = (const float*)d_in[2];
    const float* att  = (const float*)d_in[3];
    const float* cwz  = (const float*)d_in[4];
    const float* cbz  = (const float*)d_in[5];
    const float* Wz   = (const float*)d_in[6];
    const float* lbz  = (const float*)d_in[7];
    // r-gate inputs (d_in[8..11]) are mathematically dead: H=0 => R unused
    const float* cwh  = (const float*)d_in[12];
    const float* cbh  = (const float*)d_in[13];
    const float* Wh   = (const float*)d_in[14];
    const float* lbh  = (const float*)d_in[15];
    const float* wout = (const float*)d_in[16];
    const float* bout = (const float*)d_in[17];
    float* out = (float*)d_out;

    k_init<<<(N_NODES * P_DIM + 255) / 256, 256>>>();
    k_deg <<<(E_EDGES + 255) / 256, 256>>>(ei, ew);
    k_dinv<<<(N_NODES + 255) / 256, 256>>>();
    k_prep<<<1, 128>>>(cwz, cbz, Wz, lbz, cwh, cbh, Wh, lbh, att);
    k_edge<<<(E_EDGES + 255) / 256, 256>>>(ei, ew, x);
    k_node<<<N_NODES / 8, 256>>>(x, wout, bout, out);
}

// round 2
// speedup vs baseline: 1.1816x; 1.1816x over previous
#include <cuda_runtime.h>
#include <cuda_bf16.h>
#include <cstdint>

#define N_NODES 20000
#define E_EDGES 640000
#define P_DIM   12
#define H_DIM   128
#define O_DIM   12
#define H_CHUNK 8   // h-rows per CTA in k_prep

// ---------------- scratch (no dynamic allocation allowed) ----------------
__device__ float g_deg [N_NODES];
__device__ float g_dinv[N_NODES];
__device__ float g_agg [N_NODES * P_DIM];
__device__ float g_az[H_DIM], g_bz[H_DIM], g_ah[H_DIM], g_bh[H_DIM];
__device__ float g_probs[P_DIM];

// ---------------- init: deg=1 (self loop), agg=0, coeff vectors=0 ----------------
__global__ void k_init() {
    int i = blockIdx.x * blockDim.x + threadIdx.x;
    if (i < N_NODES * P_DIM) g_agg[i] = 0.0f;
    if (i < N_NODES)         g_deg[i] = 1.0f;   // self-loop weight
    if (i < H_DIM) { g_az[i] = 0.f; g_bz[i] = 0.f; g_ah[i] = 0.f; g_bh[i] = 0.f; }
}

// ---------------- degree accumulation ----------------
__global__ void k_deg(const int* __restrict__ ei, const float* __restrict__ ew) {
    int e = blockIdx.x * blockDim.x + threadIdx.x;
    if (e >= E_EDGES) return;
    int d = ei[E_EDGES + e];
    atomicAdd(&g_deg[d], ew[e]);
}

// ---------------- dinv + (thread 0) attention softmax ----------------
__global__ void k_dinv(const float* __restrict__ att) {
    int n = blockIdx.x * blockDim.x + threadIdx.x;
    if (n < N_NODES) {
        float d = g_deg[n];
        g_dinv[n] = (d > 0.0f) ? rsqrtf(d) : 0.0f;
    }
    if (blockIdx.x == 0 && threadIdx.x == 0) {
        float m = -1e30f;
        for (int p = 0; p < P_DIM; p++) m = fmaxf(m, att[p]);
        float ex[P_DIM]; float s = 0.f;
        for (int p = 0; p < P_DIM; p++) { ex[p] = __expf(att[p] - m); s += ex[p]; }
        float inv = 1.0f / s;
        for (int p = 0; p < P_DIM; p++) g_probs[p] = ex[p] * inv;
    }
}

// ---------------- fold H x H matmuls into 128-vectors (parallel over h) ----------------
__global__ void k_prep(const float* __restrict__ cwz, const float* __restrict__ cbz,
                       const float* __restrict__ Wz,  const float* __restrict__ lbz,
                       const float* __restrict__ cwh, const float* __restrict__ cbh,
                       const float* __restrict__ Wh,  const float* __restrict__ lbh) {
    int k  = threadIdx.x;              // 128 threads = coalesced along k
    int h0 = blockIdx.x * H_CHUNK;     // 16 blocks x 8 h-rows
    float az = 0.f, bz = 0.f, ah = 0.f, bh = 0.f;
#pragma unroll
    for (int i = 0; i < H_CHUNK; i++) {
        int h = h0 + i;
        float wz = Wz[h * H_DIM + k];
        float wh = Wh[h * H_DIM + k];
        az = fmaf(cwz[h], wz, az);
        bz = fmaf(cbz[h], wz, bz);
        ah = fmaf(cwh[h], wh, ah);
        bh = fmaf(cbh[h], wh, bh);
    }
    if (blockIdx.x == 0) { bz += lbz[k]; bh += lbh[k]; }  // fold linear bias once
    atomicAdd(&g_az[k], az);
    atomicAdd(&g_bz[k], bz);
    atomicAdd(&g_ah[k], ah);
    atomicAdd(&g_bh[k], bh);
}

// ---------------- edge scatter: agg[dst] += norm * x[src] ----------------
__device__ __forceinline__ void red_add_v4(float* addr, float4 v) {
    asm volatile("red.global.add.v4.f32 [%0], {%1, %2, %3, %4};"
                 :: "l"(addr), "f"(v.x), "f"(v.y), "f"(v.z), "f"(v.w)
                 : "memory");
}

__global__ void k_edge(const int* __restrict__ ei, const float* __restrict__ ew,
                       const float* __restrict__ x) {
    int e = blockIdx.x * blockDim.x + threadIdx.x;
    if (e >= E_EDGES) return;
    int s = ei[e];
    int d = ei[E_EDGES + e];
    float norm = g_dinv[s] * ew[e] * g_dinv[d];
    const float4* xr = (const float4*)(x + (size_t)s * P_DIM);   // 48B row, 16B aligned
    float*        ar = g_agg + (size_t)d * P_DIM;
#pragma unroll
    for (int j = 0; j < 3; j++) {
        float4 v = xr[j];
        v.x *= norm; v.y *= norm; v.z *= norm; v.w *= norm;
        red_add_v4(ar + 4 * j, v);
    }
}

// ---------------- node kernel: one warp per node ----------------
__global__ void __launch_bounds__(256) k_node(const float* __restrict__ x,
                                              const float* __restrict__ wout,
                                              const float* __restrict__ bout,
                                              float* __restrict__ out) {
    __shared__ float s_az[H_DIM], s_bz[H_DIM], s_ah[H_DIM], s_bh[H_DIM];
    __shared__ float s_woutT[O_DIM * H_DIM];
    __shared__ float s_probs[P_DIM], s_bout[O_DIM];

    int tid = threadIdx.x;
    for (int i = tid; i < H_DIM; i += 256) {
        s_az[i] = g_az[i]; s_bz[i] = g_bz[i];
        s_ah[i] = g_ah[i]; s_bh[i] = g_bh[i];
    }
    for (int i = tid; i < H_DIM * O_DIM; i += 256) {
        int k = i / O_DIM, o = i % O_DIM;
        s_woutT[o * H_DIM + k] = wout[i];       // transpose -> conflict-free LDS
    }
    if (tid < P_DIM) s_probs[tid] = g_probs[tid];
    if (tid < O_DIM) s_bout[tid]  = bout[tid];
    __syncthreads();

    int warp = tid >> 5, lane = tid & 31;
    int n = blockIdx.x * 8 + warp;
    if (n >= N_NODES) return;

    float dv  = g_dinv[n];
    float dv2 = dv * dv;                         // self-loop norm
    const float4* ar = (const float4*)(g_agg + (size_t)n * P_DIM);
    const float4* xr = (const float4*)(x     + (size_t)n * P_DIM);
    float a[P_DIM];
#pragma unroll
    for (int j = 0; j < 3; j++) {
        float4 av = ar[j];
        float4 xv = xr[j];
        a[4*j + 0] = fmaf(dv2, xv.x, av.x);
        a[4*j + 1] = fmaf(dv2, xv.y, av.y);
        a[4*j + 2] = fmaf(dv2, xv.z, av.z);
        a[4*j + 3] = fmaf(dv2, xv.w, av.w);
    }

    float acc[4] = {0.f, 0.f, 0.f, 0.f};
#pragma unroll
    for (int p = 0; p < P_DIM; p++) {
        float ap = a[p];
        float wp = s_probs[p];
#pragma unroll
        for (int j = 0; j < 4; j++) {
            int k = lane + 32 * j;
            // (1 - sigmoid(zs)) = 1 / (1 + exp(zs))
            float zs  = fmaf(ap, s_az[k], s_bz[k]);
            float omz = __fdividef(1.0f, 1.0f + __expf(zs));
            // tanh(hs), overflow-safe via |hs|
            float hs  = fmaf(ap, s_ah[k], s_bh[k]);
            float t   = __expf(-2.0f * fabsf(hs));
            float ht  = __fdividef(1.0f - t, 1.0f + t);
            ht = copysignf(ht, hs);
            acc[j] = fmaf(wp * omz, ht, acc[j]);
        }
    }

    // elu + out matvec (O=12)
    float o_acc[O_DIM];
#pragma unroll
    for (int o = 0; o < O_DIM; o++) o_acc[o] = 0.f;
#pragma unroll
    for (int j = 0; j < 4; j++) {
        float hk = acc[j];
        hk = (hk > 0.f) ? hk : (__expf(hk) - 1.0f);
        int k = lane + 32 * j;
#pragma unroll
        for (int o = 0; o < O_DIM; o++)
            o_acc[o] = fmaf(hk, s_woutT[o * H_DIM + k], o_acc[o]);
    }
#pragma unroll
    for (int off = 16; off > 0; off >>= 1) {
#pragma unroll
        for (int o = 0; o < O_DIM; o++)
            o_acc[o] += __shfl_xor_sync(0xffffffffu, o_acc[o], off);
    }
    if (lane == 0) {
        float* op = out + (size_t)n * O_DIM;
#pragma unroll
        for (int o = 0; o < O_DIM; o++) op[o] = o_acc[o] + s_bout[o];
    }
}

// ---------------- launch ----------------
extern "C" void kernel_launch(void* const* d_in, const int* in_sizes, int n_in,
                              void* d_out, int out_size) {
    const float* x    = (const float*)d_in[0];
    const int*   ei   = (const int*)  d_in[1];
    const float* ew   = (const float*)d_in[2];
    const float* att  = (const float*)d_in[3];
    const float* cwz  = (const float*)d_in[4];
    const float* cbz  = (const float*)d_in[5];
    const float* Wz   = (const float*)d_in[6];
    const float* lbz  = (const float*)d_in[7];
    // r-gate inputs (d_in[8..11]) are mathematically dead: H=0 => R unused
    const float* cwh  = (const float*)d_in[12];
    const float* cbh  = (const float*)d_in[13];
    const float* Wh   = (const float*)d_in[14];
    const float* lbh  = (const float*)d_in[15];
    const float* wout = (const float*)d_in[16];
    const float* bout = (const float*)d_in[17];
    float* out = (float*)d_out;

    k_init<<<(N_NODES * P_DIM + 255) / 256, 256>>>();
    k_deg <<<(E_EDGES + 255) / 256, 256>>>(ei, ew);
    k_dinv<<<(N_NODES + 255) / 256, 256>>>(att);
    k_prep<<<H_DIM / H_CHUNK, H_DIM>>>(cwz, cbz, Wz, lbz, cwh, cbh, Wh, lbh);
    k_edge<<<(E_EDGES + 255) / 256, 256>>>(ei, ew, x);
    k_node<<<N_NODES / 8, 256>>>(x, wout, bout, out);
}

// round 3
// speedup vs baseline: 1.3482x; 1.1410x over previous
#include <cuda_runtime.h>
#include <cuda_bf16.h>
#include <cstdint>

#define N_NODES 20000
#define E_EDGES 640000
#define P_DIM   12
#define H_DIM   128
#define O_DIM   12
#define DINV_BLOCKS ((N_NODES + 255) / 256)   // 79

// ---------------- scratch (no dynamic allocation allowed) ----------------
__device__ float g_deg [N_NODES];
__device__ float g_dinv[N_NODES];
__device__ float g_agg [N_NODES * P_DIM];
__device__ float g_az[H_DIM], g_bz[H_DIM], g_ah[H_DIM], g_bh[H_DIM];
__device__ float g_probs[P_DIM];

__device__ __forceinline__ float tanh_fast(float x) {
    float y;
    asm("tanh.approx.f32 %0, %1;" : "=f"(y) : "f"(x));
    return y;
}

// ---------------- init: deg=1 (self loop), agg=0 ----------------
__global__ void k_init() {
    int i = blockIdx.x * blockDim.x + threadIdx.x;
    if (i < N_NODES * P_DIM) g_agg[i] = 0.0f;
    if (i < N_NODES)         g_deg[i] = 1.0f;   // self-loop weight
}

// ---------------- degree accumulation ----------------
__global__ void k_deg(const int* __restrict__ ei, const float* __restrict__ ew) {
    int e = blockIdx.x * blockDim.x + threadIdx.x;
    if (e >= E_EDGES) return;
    int d = ei[E_EDGES + e];
    atomicAdd(&g_deg[d], ew[e]);
}

// ---------------- fused: dinv + softmax + weight-fold prep ----------------
// blocks [0, DINV_BLOCKS)   : dinv (+ softmax on block 0 thread 0)
// block DINV_BLOCKS         : fold z-gate  (az, bz)
// block DINV_BLOCKS + 1     : fold h-gate  (ah, bh)
__global__ void __launch_bounds__(256) k_dinv_prep(
        const float* __restrict__ att,
        const float* __restrict__ cwz, const float* __restrict__ cbz,
        const float* __restrict__ Wz,  const float* __restrict__ lbz,
        const float* __restrict__ cwh, const float* __restrict__ cbh,
        const float* __restrict__ Wh,  const float* __restrict__ lbh) {
    int b = blockIdx.x;
    if (b < DINV_BLOCKS) {
        int n = b * 256 + threadIdx.x;
        if (n < N_NODES) {
            float d = g_deg[n];
            g_dinv[n] = (d > 0.0f) ? rsqrtf(d) : 0.0f;
        }
        if (b == 0 && threadIdx.x == 0) {
            float m = -1e30f;
            for (int p = 0; p < P_DIM; p++) m = fmaxf(m, att[p]);
            float ex[P_DIM]; float s = 0.f;
            for (int p = 0; p < P_DIM; p++) { ex[p] = __expf(att[p] - m); s += ex[p]; }
            float inv = 1.0f / s;
            for (int p = 0; p < P_DIM; p++) g_probs[p] = ex[p] * inv;
        }
        return;
    }
    // prep: 256 threads = (k in [0,128)) x (half in {0,1}); each covers 64 h-rows.
    bool zgate = (b == DINV_BLOCKS);
    const float* cw = zgate ? cwz : cwh;
    const float* cb = zgate ? cbz : cbh;
    const float* W  = zgate ? Wz  : Wh;
    const float* lb = zgate ? lbz : lbh;
    float* ga = zgate ? g_az : g_ah;
    float* gb = zgate ? g_bz : g_bh;

    int k    = threadIdx.x & 127;
    int half = threadIdx.x >> 7;
    float pa = 0.f, pb = 0.f;
#pragma unroll 8
    for (int i = 0; i < 64; i++) {
        int h = half * 64 + i;
        float w = W[h * H_DIM + k];
        pa = fmaf(cw[h], w, pa);
        pb = fmaf(cb[h], w, pb);
    }
    __shared__ float sa[H_DIM], sb[H_DIM];
    if (half == 1) { sa[k] = pa; sb[k] = pb; }
    __syncthreads();
    if (half == 0) {
        ga[k] = pa + sa[k];
        gb[k] = pb + sb[k] + lb[k];
    }
}

// ---------------- edge scatter: agg[dst] += norm * x[src] ----------------
__device__ __forceinline__ void red_add_v4(float* addr, float4 v) {
    asm volatile("red.global.add.v4.f32 [%0], {%1, %2, %3, %4};"
                 :: "l"(addr), "f"(v.x), "f"(v.y), "f"(v.z), "f"(v.w)
                 : "memory");
}

__global__ void k_edge(const int* __restrict__ ei, const float* __restrict__ ew,
                       const float* __restrict__ x) {
    int e = blockIdx.x * blockDim.x + threadIdx.x;
    if (e >= E_EDGES) return;
    int s = ei[e];
    int d = ei[E_EDGES + e];
    float norm = g_dinv[s] * ew[e] * g_dinv[d];
    const float4* xr = (const float4*)(x + (size_t)s * P_DIM);   // 48B row, 16B aligned
    float*        ar = g_agg + (size_t)d * P_DIM;
#pragma unroll
    for (int j = 0; j < 3; j++) {
        float4 v = xr[j];
        v.x *= norm; v.y *= norm; v.z *= norm; v.w *= norm;
        red_add_v4(ar + 4 * j, v);
    }
}

// ---------------- node kernel: one warp per node ----------------
__global__ void __launch_bounds__(256) k_node(const float* __restrict__ x,
                                              const float* __restrict__ wout,
                                              const float* __restrict__ bout,
                                              float* __restrict__ out) {
    __shared__ float s_az[H_DIM], s_bz[H_DIM], s_ah[H_DIM], s_bh[H_DIM];
    __shared__ float s_woutT[O_DIM * H_DIM];
    __shared__ float s_probs[P_DIM], s_bout[O_DIM];

    int tid = threadIdx.x;
    for (int i = tid; i < H_DIM; i += 256) {
        s_az[i] = 0.5f * g_az[i];   // pre-scale for tanh(z/2) sigmoid form
        s_bz[i] = 0.5f * g_bz[i];
        s_ah[i] = g_ah[i]; s_bh[i] = g_bh[i];
    }
    for (int i = tid; i < H_DIM * O_DIM; i += 256) {
        int k = i / O_DIM, o = i % O_DIM;
        s_woutT[o * H_DIM + k] = wout[i];       // transpose -> conflict-free LDS
    }
    if (tid < P_DIM) s_probs[tid] = g_probs[tid];
    if (tid < O_DIM) s_bout[tid]  = bout[tid];
    __syncthreads();

    int warp = tid >> 5, lane = tid & 31;
    int n = blockIdx.x * 8 + warp;
    if (n >= N_NODES) return;

    float dv  = g_dinv[n];
    float dv2 = dv * dv;                         // self-loop norm
    const float4* ar = (const float4*)(g_agg + (size_t)n * P_DIM);
    const float4* xr = (const float4*)(x     + (size_t)n * P_DIM);
    float a[P_DIM];
#pragma unroll
    for (int j = 0; j < 3; j++) {
        float4 av = ar[j];
        float4 xv = xr[j];
        a[4*j + 0] = fmaf(dv2, xv.x, av.x);
        a[4*j + 1] = fmaf(dv2, xv.y, av.y);
        a[4*j + 2] = fmaf(dv2, xv.z, av.z);
        a[4*j + 3] = fmaf(dv2, xv.w, av.w);
    }

    float acc[4] = {0.f, 0.f, 0.f, 0.f};
#pragma unroll
    for (int p = 0; p < P_DIM; p++) {
        float ap = a[p];
        float wp = s_probs[p];
#pragma unroll
        for (int j = 0; j < 4; j++) {
            int k = lane + 32 * j;
            // (1 - sigmoid(2*zs')) = 0.5 - 0.5*tanh(zs')   (zs' pre-halved)
            float zs  = fmaf(ap, s_az[k], s_bz[k]);
            float omz = fmaf(-0.5f, tanh_fast(zs), 0.5f);
            float ht  = tanh_fast(fmaf(ap, s_ah[k], s_bh[k]));
            acc[j] = fmaf(wp * omz, ht, acc[j]);
        }
    }

    // elu + out matvec (O=12)
    float o_acc[O_DIM];
#pragma unroll
    for (int o = 0; o < O_DIM; o++) o_acc[o] = 0.f;
#pragma unroll
    for (int j = 0; j < 4; j++) {
        float hk = acc[j];
        hk = (hk > 0.f) ? hk : (__expf(hk) - 1.0f);
        int k = lane + 32 * j;
#pragma unroll
        for (int o = 0; o < O_DIM; o++)
            o_acc[o] = fmaf(hk, s_woutT[o * H_DIM + k], o_acc[o]);
    }
#pragma unroll
    for (int off = 16; off > 0; off >>= 1) {
#pragma unroll
        for (int o = 0; o < O_DIM; o++)
            o_acc[o] += __shfl_xor_sync(0xffffffffu, o_acc[o], off);
    }
    if (lane == 0) {
        float* op = out + (size_t)n * O_DIM;
#pragma unroll
        for (int o = 0; o < O_DIM; o++) op[o] = o_acc[o] + s_bout[o];
    }
}

// ---------------- launch ----------------
extern "C" void kernel_launch(void* const* d_in, const int* in_sizes, int n_in,
                              void* d_out, int out_size) {
    const float* x    = (const float*)d_in[0];
    const int*   ei   = (const int*)  d_in[1];
    const float* ew   = (const float*)d_in[2];
    const float* att  = (const float*)d_in[3];
    const float* cwz  = (const float*)d_in[4];
    const float* cbz  = (const float*)d_in[5];
    const float* Wz   = (const float*)d_in[6];
    const float* lbz  = (const float*)d_in[7];
    // r-gate inputs (d_in[8..11]) are mathematically dead: H=0 => R unused
    const float* cwh  = (const float*)d_in[12];
    const float* cbh  = (const float*)d_in[13];
    const float* Wh   = (const float*)d_in[14];
    const float* lbh  = (const float*)d_in[15];
    const float* wout = (const float*)d_in[16];
    const float* bout = (const float*)d_in[17];
    float* out = (float*)d_out;

    k_init<<<(N_NODES * P_DIM + 255) / 256, 256>>>();
    k_deg <<<(E_EDGES + 255) / 256, 256>>>(ei, ew);
    k_dinv_prep<<<DINV_BLOCKS + 2, 256>>>(att, cwz, cbz, Wz, lbz,
                                          cwh, cbh, Wh, lbh);
    k_edge<<<(E_EDGES + 255) / 256, 256>>>(ei, ew, x);
    k_node<<<N_NODES / 8, 256>>>(x, wout, bout, out);
}

// round 4
// speedup vs baseline: 1.4120x; 1.0473x over previous
#include <cuda_runtime.h>
#include <cuda_bf16.h>
#include <cstdint>

#define N_NODES 20000
#define E_EDGES 640000
#define P_DIM   12
#define H_DIM   128
#define O_DIM   12
#define DINV_BLOCKS ((N_NODES + 255) / 256)   // 79

// ---------------- scratch (no dynamic allocation allowed) ----------------
__device__ float g_deg [N_NODES];
__device__ float g_dinv[N_NODES];
__device__ float g_xs  [N_NODES * P_DIM];   // dinv[n] * x[n,:]
__device__ float g_agg [N_NODES * P_DIM];   // un-dst-normalized aggregate
__device__ float g_az[H_DIM], g_bz[H_DIM], g_ah[H_DIM], g_bh[H_DIM];
__device__ float g_probs[P_DIM];

__device__ __forceinline__ float tanh_fast(float x) {
    float y;
    asm("tanh.approx.f32 %0, %1;" : "=f"(y) : "f"(x));
    return y;
}

// ---------------- init: deg=1 (self loop), agg=0 ----------------
__global__ void k_init() {
    int i = blockIdx.x * blockDim.x + threadIdx.x;
    if (i < N_NODES * P_DIM) g_agg[i] = 0.0f;
    if (i < N_NODES)         g_deg[i] = 1.0f;   // self-loop weight
}

// ---------------- degree accumulation ----------------
__global__ void k_deg(const int* __restrict__ ei, const float* __restrict__ ew) {
    int e = blockIdx.x * blockDim.x + threadIdx.x;
    if (e >= E_EDGES) return;
    int d = ei[E_EDGES + e];
    atomicAdd(&g_deg[d], ew[e]);
}

// ---------------- fused: dinv + xs prescale + softmax + weight-fold ----------------
// blocks [0, DINV_BLOCKS)   : dinv + xs[n,:] = dinv[n]*x[n,:]  (+softmax b0/t0)
// block DINV_BLOCKS         : fold z-gate  (az, bz)
// block DINV_BLOCKS + 1     : fold h-gate  (ah, bh)
__global__ void __launch_bounds__(256) k_dinv_prep(
        const float* __restrict__ x,   const float* __restrict__ att,
        const float* __restrict__ cwz, const float* __restrict__ cbz,
        const float* __restrict__ Wz,  const float* __restrict__ lbz,
        const float* __restrict__ cwh, const float* __restrict__ cbh,
        const float* __restrict__ Wh,  const float* __restrict__ lbh) {
    int b = blockIdx.x;
    int tid = threadIdx.x;
    if (b < DINV_BLOCKS) {
        __shared__ float s_dinv[256];
        int n0 = b * 256;
        int n  = n0 + tid;
        float dv = 0.0f;
        if (n < N_NODES) {
            float d = g_deg[n];
            dv = (d > 0.0f) ? rsqrtf(d) : 0.0f;
            g_dinv[n] = dv;
        }
        s_dinv[tid] = dv;
        __syncthreads();
        // coalesced prescale: xs = dinv * x over this block's 256 rows
        int base  = n0 * P_DIM;
        int count = min(256, N_NODES - n0) * P_DIM;
        for (int j = tid; j < count; j += 256) {
            g_xs[base + j] = s_dinv[j / P_DIM] * x[base + j];
        }
        if (b == 0 && tid == 0) {
            float m = -1e30f;
            for (int p = 0; p < P_DIM; p++) m = fmaxf(m, att[p]);
            float ex[P_DIM]; float s = 0.f;
            for (int p = 0; p < P_DIM; p++) { ex[p] = __expf(att[p] - m); s += ex[p]; }
            float inv = 1.0f / s;
            for (int p = 0; p < P_DIM; p++) g_probs[p] = ex[p] * inv;
        }
        return;
    }
    // prep: 256 threads = (k in [0,128)) x (half in {0,1}); each covers 64 h-rows.
    bool zgate = (b == DINV_BLOCKS);
    const float* cw = zgate ? cwz : cwh;
    const float* cb = zgate ? cbz : cbh;
    const float* W  = zgate ? Wz  : Wh;
    const float* lb = zgate ? lbz : lbh;
    float* ga = zgate ? g_az : g_ah;
    float* gb = zgate ? g_bz : g_bh;

    int k    = tid & 127;
    int half = tid >> 7;
    float pa = 0.f, pb = 0.f;
#pragma unroll 8
    for (int i = 0; i < 64; i++) {
        int h = half * 64 + i;
        float w = W[h * H_DIM + k];
        pa = fmaf(cw[h], w, pa);
        pb = fmaf(cb[h], w, pb);
    }
    __shared__ float sa[H_DIM], sb[H_DIM];
    if (half == 1) { sa[k] = pa; sb[k] = pb; }
    __syncthreads();
    if (half == 0) {
        ga[k] = pa + sa[k];
        gb[k] = pb + sb[k] + lb[k];
    }
}

// ---------------- edge scatter: agg[dst] += w * xs[src]  (no dinv loads) ----------------
__device__ __forceinline__ void red_add_v4(float* addr, float4 v) {
    asm volatile("red.global.add.v4.f32 [%0], {%1, %2, %3, %4};"
                 :: "l"(addr), "f"(v.x), "f"(v.y), "f"(v.z), "f"(v.w)
                 : "memory");
}

__global__ void k_edge(const int* __restrict__ ei, const float* __restrict__ ew) {
    int e = blockIdx.x * blockDim.x + threadIdx.x;
    if (e >= E_EDGES) return;
    int s = ei[e];
    int d = ei[E_EDGES + e];
    float w = ew[e];
    const float4* xr = (const float4*)(g_xs + (size_t)s * P_DIM);   // 48B row, 16B aligned
    float*        ar = g_agg + (size_t)d * P_DIM;
#pragma unroll
    for (int j = 0; j < 3; j++) {
        float4 v = xr[j];
        v.x *= w; v.y *= w; v.z *= w; v.w *= w;
        red_add_v4(ar + 4 * j, v);
    }
}

// ---------------- node kernel: one warp per node ----------------
__global__ void __launch_bounds__(256) k_node(const float* __restrict__ wout,
                                              const float* __restrict__ bout,
                                              float* __restrict__ out) {
    __shared__ float s_az[H_DIM], s_bz[H_DIM], s_ah[H_DIM], s_bh[H_DIM];
    __shared__ float s_woutT[O_DIM * H_DIM];
    __shared__ float s_probs[P_DIM], s_bout[O_DIM];

    int tid = threadIdx.x;
    for (int i = tid; i < H_DIM; i += 256) {
        s_az[i] = 0.5f * g_az[i];   // pre-scale for tanh(z/2) sigmoid form
        s_bz[i] = 0.5f * g_bz[i];
        s_ah[i] = g_ah[i]; s_bh[i] = g_bh[i];
    }
    for (int i = tid; i < H_DIM * O_DIM; i += 256) {
        int k = i / O_DIM, o = i % O_DIM;
        s_woutT[o * H_DIM + k] = wout[i];       // transpose -> conflict-free LDS
    }
    if (tid < P_DIM) s_probs[tid] = g_probs[tid];
    if (tid < O_DIM) s_bout[tid]  = bout[tid];
    __syncthreads();

    int warp = tid >> 5, lane = tid & 31;
    int n = blockIdx.x * 8 + warp;
    if (n >= N_NODES) return;

    float dv = g_dinv[n];
    // a = dv * (agg_raw + xs)   ( == dinv[d]*agg_normalized + dinv^2 * x )
    const float4* ar  = (const float4*)(g_agg + (size_t)n * P_DIM);
    const float4* xsr = (const float4*)(g_xs  + (size_t)n * P_DIM);
    float a[P_DIM];
#pragma unroll
    for (int j = 0; j < 3; j++) {
        float4 av = ar[j];
        float4 xv = xsr[j];
        a[4*j + 0] = dv * (av.x + xv.x);
        a[4*j + 1] = dv * (av.y + xv.y);
        a[4*j + 2] = dv * (av.z + xv.z);
        a[4*j + 3] = dv * (av.w + xv.w);
    }

    float acc[4] = {0.f, 0.f, 0.f, 0.f};
#pragma unroll
    for (int p = 0; p < P_DIM; p++) {
        float ap = a[p];
        float wp = s_probs[p];
#pragma unroll
        for (int j = 0; j < 4; j++) {
            int k = lane + 32 * j;
            // (1 - sigmoid(2*zs')) = 0.5 - 0.5*tanh(zs')   (zs' pre-halved)
            float zs  = fmaf(ap, s_az[k], s_bz[k]);
            float omz = fmaf(-0.5f, tanh_fast(zs), 0.5f);
            float ht  = tanh_fast(fmaf(ap, s_ah[k], s_bh[k]));
            acc[j] = fmaf(wp * omz, ht, acc[j]);
        }
    }

    // elu + out matvec (O=12)
    float o_acc[O_DIM];
#pragma unroll
    for (int o = 0; o < O_DIM; o++) o_acc[o] = 0.f;
#pragma unroll
    for (int j = 0; j < 4; j++) {
        float hk = acc[j];
        hk = (hk > 0.f) ? hk : (__expf(hk) - 1.0f);
        int k = lane + 32 * j;
#pragma unroll
        for (int o = 0; o < O_DIM; o++)
            o_acc[o] = fmaf(hk, s_woutT[o * H_DIM + k], o_acc[o]);
    }
#pragma unroll
    for (int off = 16; off > 0; off >>= 1) {
#pragma unroll
        for (int o = 0; o < O_DIM; o++)
            o_acc[o] += __shfl_xor_sync(0xffffffffu, o_acc[o], off);
    }
    if (lane == 0) {
        float* op = out + (size_t)n * O_DIM;
#pragma unroll
        for (int o = 0; o < O_DIM; o++) op[o] = o_acc[o] + s_bout[o];
    }
}

// ---------------- launch ----------------
extern "C" void kernel_launch(void* const* d_in, const int* in_sizes, int n_in,
                              void* d_out, int out_size) {
    const float* x    = (const float*)d_in[0];
    const int*   ei   = (const int*)  d_in[1];
    const float* ew   = (const float*)d_in[2];
    const float* att  = (const float*)d_in[3];
    const float* cwz  = (const float*)d_in[4];
    const float* cbz  = (const float*)d_in[5];
    const float* Wz   = (const float*)d_in[6];
    const float* lbz  = (const float*)d_in[7];
    // r-gate inputs (d_in[8..11]) are mathematically dead: H=0 => R unused
    const float* cwh  = (const float*)d_in[12];
    const float* cbh  = (const float*)d_in[13];
    const float* Wh   = (const float*)d_in[14];
    const float* lbh  = (const float*)d_in[15];
    const float* wout = (const float*)d_in[16];
    const float* bout = (const float*)d_in[17];
    float* out = (float*)d_out;

    k_init<<<(N_NODES * P_DIM + 255) / 256, 256>>>();
    k_deg <<<(E_EDGES + 255) / 256, 256>>>(ei, ew);
    k_dinv_prep<<<DINV_BLOCKS + 2, 256>>>(x, att, cwz, cbz, Wz, lbz,
                                          cwh, cbh, Wh, lbh);
    k_edge<<<(E_EDGES + 255) / 256, 256>>>(ei, ew);
    k_node<<<N_NODES / 8, 256>>>(wout, bout, out);
}

// round 5
// speedup vs baseline: 1.6216x; 1.1484x over previous
#include <cuda_runtime.h>
#include <cuda_bf16.h>
#include <cstdint>

#define N_NODES 20000
#define E_EDGES 640000
#define P_DIM   12
#define H_DIM   128
#define O_DIM   12
#define DINV_BLOCKS ((N_NODES + 255) / 256)   // 79
#define EDGES_PER_WARP 10                     // 3 lanes per edge, 2 idle lanes

// ---------------- scratch (no dynamic allocation; zero-initialized at load) ----------------
// INVARIANT: g_deg and g_agg are all-zero at entry of every kernel_launch call
// (zeroed at module load, re-zeroed inside each launch after consumption).
__device__ float g_deg [N_NODES];
__device__ float g_dinv[N_NODES];
__device__ float g_xs  [N_NODES * P_DIM];   // dinv[n] * x[n,:]
__device__ float g_agg [N_NODES * P_DIM];   // un-dst-normalized aggregate
__device__ float g_az[H_DIM], g_bz[H_DIM], g_ah[H_DIM], g_bh[H_DIM];
__device__ float g_probs[P_DIM];

__device__ __forceinline__ float tanh_fast(float x) {
    float y;
    asm("tanh.approx.f32 %0, %1;" : "=f"(y) : "f"(x));
    return y;
}

// ---------------- degree accumulation (g_deg starts at 0; +1 folded into dinv) ----------------
__global__ void k_deg(const int* __restrict__ ei, const float* __restrict__ ew) {
    int t = blockIdx.x * blockDim.x + threadIdx.x;
    int e2 = t * 2;
    if (e2 >= E_EDGES) return;
    int2   d = *(const int2*)  (ei + E_EDGES + e2);
    float2 w = *(const float2*)(ew + e2);
    atomicAdd(&g_deg[d.x], w.x);
    atomicAdd(&g_deg[d.y], w.y);
}

// ---------------- fused: dinv(+deg reset) + xs prescale + softmax + weight-fold ----------------
// blocks [0, DINV_BLOCKS)   : dinv + xs[n,:] = dinv[n]*x[n,:]  (+softmax b0/t0)
// block DINV_BLOCKS         : fold z-gate  (az, bz)
// block DINV_BLOCKS + 1     : fold h-gate  (ah, bh)
__global__ void __launch_bounds__(256) k_dinv_prep(
        const float* __restrict__ x,   const float* __restrict__ att,
        const float* __restrict__ cwz, const float* __restrict__ cbz,
        const float* __restrict__ Wz,  const float* __restrict__ lbz,
        const float* __restrict__ cwh, const float* __restrict__ cbh,
        const float* __restrict__ Wh,  const float* __restrict__ lbh) {
    int b = blockIdx.x;
    int tid = threadIdx.x;
    if (b < DINV_BLOCKS) {
        __shared__ float s_dinv[256];
        int n0 = b * 256;
        int n  = n0 + tid;
        float dv = 0.0f;
        if (n < N_NODES) {
            float d = g_deg[n] + 1.0f;       // self-loop weight folded here
            dv = rsqrtf(d);                  // d >= 1 > 0 always
            g_dinv[n] = dv;
            g_deg[n]  = 0.0f;                // reset for next launch (replay-safe)
        }
        s_dinv[tid] = dv;
        __syncthreads();
        // coalesced prescale: xs = dinv * x over this block's 256 rows
        int base  = n0 * P_DIM;
        int count = min(256, N_NODES - n0) * P_DIM;
        for (int j = tid; j < count; j += 256) {
            g_xs[base + j] = s_dinv[j / P_DIM] * x[base + j];
        }
        if (b == 0 && tid == 0) {
            float m = -1e30f;
            for (int p = 0; p < P_DIM; p++) m = fmaxf(m, att[p]);
            float ex[P_DIM]; float s = 0.f;
            for (int p = 0; p < P_DIM; p++) { ex[p] = __expf(att[p] - m); s += ex[p]; }
            float inv = 1.0f / s;
            for (int p = 0; p < P_DIM; p++) g_probs[p] = ex[p] * inv;
        }
        return;
    }
    // prep: 256 threads = (k in [0,128)) x (half in {0,1}); each covers 64 h-rows.
    bool zgate = (b == DINV_BLOCKS);
    const float* cw = zgate ? cwz : cwh;
    const float* cb = zgate ? cbz : cbh;
    const float* W  = zgate ? Wz  : Wh;
    const float* lb = zgate ? lbz : lbh;
    float* ga = zgate ? g_az : g_ah;
    float* gb = zgate ? g_bz : g_bh;

    int k    = tid & 127;
    int half = tid >> 7;
    float pa = 0.f, pb = 0.f;
#pragma unroll 8
    for (int i = 0; i < 64; i++) {
        int h = half * 64 + i;
        float w = W[h * H_DIM + k];
        pa = fmaf(cw[h], w, pa);
        pb = fmaf(cb[h], w, pb);
    }
    __shared__ float sa[H_DIM], sb[H_DIM];
    if (half == 1) { sa[k] = pa; sb[k] = pb; }
    __syncthreads();
    if (half == 0) {
        ga[k] = pa + sa[k];
        gb[k] = pb + sb[k] + lb[k];
    }
}

// ---------------- edge scatter: 3 lanes per edge -> min sector count ----------------
__device__ __forceinline__ void red_add_v4(float* addr, float4 v) {
    asm volatile("red.global.add.v4.f32 [%0], {%1, %2, %3, %4};"
                 :: "l"(addr), "f"(v.x), "f"(v.y), "f"(v.z), "f"(v.w)
                 : "memory");
}

__global__ void __launch_bounds__(256) k_edge(const int* __restrict__ ei,
                                              const float* __restrict__ ew) {
    int warp_g = (blockIdx.x * blockDim.x + threadIdx.x) >> 5;
    int lane   = threadIdx.x & 31;
    if (lane >= 3 * EDGES_PER_WARP) return;          // 2 idle lanes per warp
    int el = lane / 3;                                // edge-in-warp 0..9
    int j  = lane - el * 3;                           // quarter index 0..2
    int e  = warp_g * EDGES_PER_WARP + el;
    if (e >= E_EDGES) return;
    int   s = __ldg(ei + e);
    int   d = __ldg(ei + E_EDGES + e);
    float w = __ldg(ew + e);
    float4 v = *(const float4*)(g_xs + (size_t)s * P_DIM + 4 * j);
    v.x *= w; v.y *= w; v.z *= w; v.w *= w;
    red_add_v4(g_agg + (size_t)d * P_DIM + 4 * j, v);
}

// ---------------- node kernel: one warp per node (+agg reset for next launch) ----------------
__global__ void __launch_bounds__(256) k_node(const float* __restrict__ wout,
                                              const float* __restrict__ bout,
                                              float* __restrict__ out) {
    __shared__ float s_az[H_DIM], s_bz[H_DIM], s_ah[H_DIM], s_bh[H_DIM];
    __shared__ float s_woutT[O_DIM * H_DIM];
    __shared__ float s_probs[P_DIM], s_bout[O_DIM];

    int tid = threadIdx.x;
    for (int i = tid; i < H_DIM; i += 256) {
        s_az[i] = 0.5f * g_az[i];   // pre-scale for tanh(z/2) sigmoid form
        s_bz[i] = 0.5f * g_bz[i];
        s_ah[i] = g_ah[i]; s_bh[i] = g_bh[i];
    }
    for (int i = tid; i < H_DIM * O_DIM; i += 256) {
        int k = i / O_DIM, o = i % O_DIM;
        s_woutT[o * H_DIM + k] = wout[i];       // transpose -> conflict-free LDS
    }
    if (tid < P_DIM) s_probs[tid] = g_probs[tid];
    if (tid < O_DIM) s_bout[tid]  = bout[tid];
    __syncthreads();

    int warp = tid >> 5, lane = tid & 31;
    int n = blockIdx.x * 8 + warp;
    if (n >= N_NODES) return;

    float dv = g_dinv[n];
    // a = dv * (agg_raw + xs)   ( == dinv[d]*agg_normalized + dinv^2 * x )
    float4*       ar  = (float4*)(g_agg + (size_t)n * P_DIM);
    const float4* xsr = (const float4*)(g_xs + (size_t)n * P_DIM);
    float a[P_DIM];
#pragma unroll
    for (int j = 0; j < 3; j++) {
        float4 av = ar[j];
        float4 xv = xsr[j];
        a[4*j + 0] = dv * (av.x + xv.x);
        a[4*j + 1] = dv * (av.y + xv.y);
        a[4*j + 2] = dv * (av.z + xv.z);
        a[4*j + 3] = dv * (av.w + xv.w);
    }
    // reset agg row for next launch (after all lanes have loaded it)
    if (lane < 3) ar[lane] = make_float4(0.f, 0.f, 0.f, 0.f);

    float acc[4] = {0.f, 0.f, 0.f, 0.f};
#pragma unroll
    for (int p = 0; p < P_DIM; p++) {
        float ap = a[p];
        float wp = s_probs[p];
#pragma unroll
        for (int j = 0; j < 4; j++) {
            int k = lane + 32 * j;
            // (1 - sigmoid(2*zs')) = 0.5 - 0.5*tanh(zs')   (zs' pre-halved)
            float zs  = fmaf(ap, s_az[k], s_bz[k]);
            float omz = fmaf(-0.5f, tanh_fast(zs), 0.5f);
            float ht  = tanh_fast(fmaf(ap, s_ah[k], s_bh[k]));
            acc[j] = fmaf(wp * omz, ht, acc[j]);
        }
    }

    // elu + out matvec (O=12)
    float o_acc[O_DIM];
#pragma unroll
    for (int o = 0; o < O_DIM; o++) o_acc[o] = 0.f;
#pragma unroll
    for (int j = 0; j < 4; j++) {
        float hk = acc[j];
        hk = (hk > 0.f) ? hk : (__expf(hk) - 1.0f);
        int k = lane + 32 * j;
#pragma unroll
        for (int o = 0; o < O_DIM; o++)
            o_acc[o] = fmaf(hk, s_woutT[o * H_DIM + k], o_acc[o]);
    }
#pragma unroll
    for (int off = 16; off > 0; off >>= 1) {
#pragma unroll
        for (int o = 0; o < O_DIM; o++)
            o_acc[o] += __shfl_xor_sync(0xffffffffu, o_acc[o], off);
    }
    if (lane == 0) {
        float* op = out + (size_t)n * O_DIM;
#pragma unroll
        for (int o = 0; o < O_DIM; o++) op[o] = o_acc[o] + s_bout[o];
    }
}

// ---------------- launch ----------------
extern "C" void kernel_launch(void* const* d_in, const int* in_sizes, int n_in,
                              void* d_out, int out_size) {
    const float* x    = (const float*)d_in[0];
    const int*   ei   = (const int*)  d_in[1];
    const float* ew   = (const float*)d_in[2];
    const float* att  = (const float*)d_in[3];
    const float* cwz  = (const float*)d_in[4];
    const float* cbz  = (const float*)d_in[5];
    const float* Wz   = (const float*)d_in[6];
    const float* lbz  = (const float*)d_in[7];
    // r-gate inputs (d_in[8..11]) are mathematically dead: H=0 => R unused
    const float* cwh  = (const float*)d_in[12];
    const float* cbh  = (const float*)d_in[13];
    const float* Wh   = (const float*)d_in[14];
    const float* lbh  = (const float*)d_in[15];
    const float* wout = (const float*)d_in[16];
    const float* bout = (const float*)d_in[17];
    float* out = (float*)d_out;

    k_deg <<<(E_EDGES / 2 + 255) / 256, 256>>>(ei, ew);
    k_dinv_prep<<<DINV_BLOCKS + 2, 256>>>(x, att, cwz, cbz, Wz, lbz,
                                          cwh, cbh, Wh, lbh);
    int edge_warps  = (E_EDGES + EDGES_PER_WARP - 1) / EDGES_PER_WARP;   // 64000
    int edge_blocks = (edge_warps + 7) / 8;                               // 8000
    k_edge<<<edge_blocks, 256>>>(ei, ew);
    k_node<<<N_NODES / 8, 256>>>(wout, bout, out);
}